// round 1
// baseline (speedup 1.0000x reference)
#include <cuda_runtime.h>
#include <math.h>

// Problem constants
namespace {
constexpr int B = 4;
constexpr int T = 2048;
constexpr int D = 1024;      // D_IN == D_OUT
constexpr int MPROJ = B * T; // 8192

// Scratch (allocation-free: __device__ globals)
__device__ float g_q[(size_t)B * T * D]; // 32 MB
__device__ float g_k[(size_t)B * T * D]; // 32 MB
__device__ float g_v[(size_t)B * T * D]; // 32 MB
__device__ float g_p[(size_t)B * T * T]; // 64 MB: scores, then probs in-place
} // namespace

// ---------------------------------------------------------------------------
// Classic 128x128x8 fp32 SGEMM tile, 256 threads, 8x8 microtile per thread.
// TRANS_B = false: C[m,n] += A[m,k] * Bp[k,n]   (A: MxK rm, Bp: KxN rm)
// TRANS_B = true : C[m,n] += A[m,k] * Bp[n,k]   (A: MxK rm, Bp: NxK rm)
// All tile dims assumed to divide exactly (true for this problem).
// ---------------------------------------------------------------------------
template <bool TRANS_B>
__device__ __forceinline__ void sgemm_tile(const float* __restrict__ A,
                                           const float* __restrict__ Bp,
                                           float* __restrict__ C,
                                           int lda, int ldb, int ldc,
                                           int bm, int bn, int kTiles) {
    __shared__ float As[8][128];
    __shared__ float Bs[8][128];

    const int tid = threadIdx.x;

    // A tile load pattern: 128 rows x 8 cols = 256 float4 (transposed store)
    const int arow = tid >> 1;         // 0..127
    const int acol = (tid & 1) * 4;    // 0 or 4

    // B tile load pattern (NN): 8 rows x 128 cols = 256 float4 (direct store)
    const int brow = tid >> 5;         // 0..7
    const int bcol = (tid & 31) * 4;   // 0..124

    // Microtile coordinates: 16x16 thread grid, each thread 8x8
    const int tr = (tid >> 4) * 8;     // 0..120
    const int tc = (tid & 15) * 8;     // 0..120

    float acc[8][8];
#pragma unroll
    for (int i = 0; i < 8; i++)
#pragma unroll
        for (int j = 0; j < 8; j++) acc[i][j] = 0.0f;

    for (int t = 0; t < kTiles; ++t) {
        const int k0 = t * 8;

        // Load A tile (transpose into As[k][m])
        {
            const float4 a4 = *reinterpret_cast<const float4*>(
                A + (size_t)(bm + arow) * lda + (k0 + acol));
            As[acol + 0][arow] = a4.x;
            As[acol + 1][arow] = a4.y;
            As[acol + 2][arow] = a4.z;
            As[acol + 3][arow] = a4.w;
        }
        // Load B tile
        if (!TRANS_B) {
            const float4 b4 = *reinterpret_cast<const float4*>(
                Bp + (size_t)(k0 + brow) * ldb + (bn + bcol));
            *reinterpret_cast<float4*>(&Bs[brow][bcol]) = b4;
        } else {
            // Bp is [N x K] row-major: same pattern as A, transposed store
            const float4 b4 = *reinterpret_cast<const float4*>(
                Bp + (size_t)(bn + arow) * ldb + (k0 + acol));
            Bs[acol + 0][arow] = b4.x;
            Bs[acol + 1][arow] = b4.y;
            Bs[acol + 2][arow] = b4.z;
            Bs[acol + 3][arow] = b4.w;
        }
        __syncthreads();

#pragma unroll
        for (int k = 0; k < 8; ++k) {
            float ra[8], rb[8];
            const float4 a0 = *reinterpret_cast<const float4*>(&As[k][tr]);
            const float4 a1 = *reinterpret_cast<const float4*>(&As[k][tr + 4]);
            const float4 b0 = *reinterpret_cast<const float4*>(&Bs[k][tc]);
            const float4 b1 = *reinterpret_cast<const float4*>(&Bs[k][tc + 4]);
            ra[0] = a0.x; ra[1] = a0.y; ra[2] = a0.z; ra[3] = a0.w;
            ra[4] = a1.x; ra[5] = a1.y; ra[6] = a1.z; ra[7] = a1.w;
            rb[0] = b0.x; rb[1] = b0.y; rb[2] = b0.z; rb[3] = b0.w;
            rb[4] = b1.x; rb[5] = b1.y; rb[6] = b1.z; rb[7] = b1.w;
#pragma unroll
            for (int i = 0; i < 8; ++i)
#pragma unroll
                for (int j = 0; j < 8; ++j)
                    acc[i][j] = fmaf(ra[i], rb[j], acc[i][j]);
        }
        __syncthreads();
    }

    // Epilogue
#pragma unroll
    for (int i = 0; i < 8; ++i) {
        float4 o0, o1;
        o0.x = acc[i][0]; o0.y = acc[i][1]; o0.z = acc[i][2]; o0.w = acc[i][3];
        o1.x = acc[i][4]; o1.y = acc[i][5]; o1.z = acc[i][6]; o1.w = acc[i][7];
        float* crow = C + (size_t)(bm + tr + i) * ldc + (bn + tc);
        *reinterpret_cast<float4*>(crow) = o0;
        *reinterpret_cast<float4*>(crow + 4) = o1;
    }
}

// ---------------------------------------------------------------------------
// Kernel 1: fused QKV projection. X[8192,1024] @ W[1024,1024] for 3 weights.
// grid: (N/128=8, M/128=64, 3)
// ---------------------------------------------------------------------------
__global__ __launch_bounds__(256) void proj_kernel(
    const float* __restrict__ X,
    const float* __restrict__ Wq,
    const float* __restrict__ Wk,
    const float* __restrict__ Wv) {
    const float* W = (blockIdx.z == 0) ? Wq : (blockIdx.z == 1) ? Wk : Wv;
    float* C = (blockIdx.z == 0) ? g_q : (blockIdx.z == 1) ? g_k : g_v;
    sgemm_tile<false>(X, W, C, D, D, D,
                      blockIdx.y * 128, blockIdx.x * 128, D / 8);
}

// ---------------------------------------------------------------------------
// Kernel 2: scores S[b] = Q[b] @ K[b]^T (NT). Causal: skip tiles fully above
// the diagonal (kn > qm). Entries above the diagonal inside the diagonal tile
// are computed but ignored by softmax.
// grid: (T/128=16 kn, T/128=16 qm, B)
// ---------------------------------------------------------------------------
__global__ __launch_bounds__(256) void scores_kernel() {
    const int qm = blockIdx.y;
    const int kn = blockIdx.x;
    if (kn > qm) return;
    const int b = blockIdx.z;
    const float* Q = g_q + (size_t)b * T * D;
    const float* Kp = g_k + (size_t)b * T * D;
    float* S = g_p + (size_t)b * T * T;
    sgemm_tile<true>(Q, Kp, S, D, D, T, qm * 128, kn * 128, D / 8);
}

// ---------------------------------------------------------------------------
// Kernel 3: row softmax, in place on g_p. Row (b,q): valid range k in [0, q].
// Scale 1/sqrt(D)=1/32 applied pre-softmax. Writes exact zeros for k > q so
// the PV GEMM needs no masking.
// grid: (B*T) blocks of 256 threads.
// ---------------------------------------------------------------------------
__global__ __launch_bounds__(256) void softmax_kernel() {
    __shared__ float buf[T];    // 8 KB: exp values for this row
    __shared__ float red[256];

    const int row = blockIdx.x;
    const int b = row / T;
    const int q = row % T;
    float* S = g_p + (size_t)b * T * T + (size_t)q * T;

    const int tid = threadIdx.x;
    const int n = q + 1;              // valid length
    const float scale = 0.03125f;     // 1/sqrt(1024)

    // Pass 1: max of scaled scores
    float m = -INFINITY;
    for (int k = tid; k < n; k += 256) m = fmaxf(m, S[k] * scale);
    red[tid] = m;
    __syncthreads();
    for (int s = 128; s > 0; s >>= 1) {
        if (tid < s) red[tid] = fmaxf(red[tid], red[tid + s]);
        __syncthreads();
    }
    m = red[0];
    __syncthreads();

    // Pass 2: exp + sum
    float lsum = 0.0f;
    for (int k = tid; k < n; k += 256) {
        const float e = expf(S[k] * scale - m);
        buf[k] = e;
        lsum += e;
    }
    red[tid] = lsum;
    __syncthreads();
    for (int s = 128; s > 0; s >>= 1) {
        if (tid < s) red[tid] += red[tid + s];
        __syncthreads();
    }
    const float inv = 1.0f / red[0];
    __syncthreads();

    // Pass 3: write normalized probs; zero the masked tail
    for (int k = tid; k < T; k += 256)
        S[k] = (k < n) ? buf[k] * inv : 0.0f;
}

// ---------------------------------------------------------------------------
// Kernel 4: O[b] = P[b] @ V[b] (NN). k-loop truncated at the diagonal:
// for query block qm, k <= qm*128+127 suffices (P is zero beyond).
// grid: (D/128=8, T/128=16 qm, B)
// ---------------------------------------------------------------------------
__global__ __launch_bounds__(256) void pv_kernel(float* __restrict__ O) {
    const int b = blockIdx.z;
    const int qm = blockIdx.y;
    const float* P = g_p + (size_t)b * T * T;
    const float* V = g_v + (size_t)b * T * D;
    float* Cb = O + (size_t)b * T * D;
    const int kTiles = (qm + 1) * (128 / 8); // (qm+1)*16 tiles of BK=8
    sgemm_tile<false>(P, V, Cb, T, D, D, qm * 128, blockIdx.x * 128, kTiles);
}

// ---------------------------------------------------------------------------
extern "C" void kernel_launch(void* const* d_in, const int* in_sizes, int n_in,
                              void* d_out, int out_size) {
    (void)in_sizes; (void)n_in; (void)out_size;
    const float* X  = (const float*)d_in[0];
    const float* Wq = (const float*)d_in[1];
    const float* Wk = (const float*)d_in[2];
    const float* Wv = (const float*)d_in[3];
    float* O = (float*)d_out;

    dim3 blk(256);
    proj_kernel<<<dim3(D / 128, MPROJ / 128, 3), blk>>>(X, Wq, Wk, Wv);
    scores_kernel<<<dim3(T / 128, T / 128, B), blk>>>();
    softmax_kernel<<<dim3(B * T), blk>>>();
    pv_kernel<<<dim3(D / 128, T / 128, B), blk>>>(O);
}

// round 2
// speedup vs baseline: 2.0589x; 2.0589x over previous
#include <cuda_runtime.h>
#include <math.h>
#include <stdint.h>

// Problem constants
namespace {
constexpr int B = 4;
constexpr int T = 2048;
constexpr int D = 1024;      // D_IN == D_OUT
constexpr int MPROJ = B * T; // 8192

// Scratch (allocation-free: __device__ globals)
__device__ float g_q[(size_t)B * T * D]; // 32 MB
__device__ float g_k[(size_t)B * T * D]; // 32 MB
__device__ float g_v[(size_t)B * T * D]; // 32 MB
__device__ float g_p[(size_t)B * T * T]; // 64 MB: scores, then probs in-place
} // namespace

__device__ __forceinline__ uint32_t f2tf32(float x) {
    uint32_t r;
    asm("cvt.rna.tf32.f32 %0, %1;" : "=r"(r) : "f"(x));
    return r;
}

__device__ __forceinline__ void mma_tf32(float c[4], const uint32_t a[4],
                                         const uint32_t b[2]) {
    asm volatile(
        "mma.sync.aligned.m16n8k8.row.col.f32.tf32.tf32.f32 "
        "{%0,%1,%2,%3}, {%4,%5,%6,%7}, {%8,%9}, {%0,%1,%2,%3};"
        : "+f"(c[0]), "+f"(c[1]), "+f"(c[2]), "+f"(c[3])
        : "r"(a[0]), "r"(a[1]), "r"(a[2]), "r"(a[3]), "r"(b[0]), "r"(b[1]));
}

// ---------------------------------------------------------------------------
// tf32 tensor-core GEMM tile: 128x128 per CTA, BK=16, 256 threads (8 warps).
// Warp grid 4x2; each warp computes 32x64 via 2x8 m16n8k8 mma tiles.
// TRANS_B = false: C[m,n] += A[m,k] * Bp[k,n]   (A: MxK rm, Bp: KxN rm)
// TRANS_B = true : C[m,n] += A[m,k] * Bp[n,k]   (A: MxK rm, Bp: NxK rm)
// All tile dims divide exactly for this problem.
// ---------------------------------------------------------------------------
template <bool TRANS_B>
__device__ __forceinline__ void mma_gemm_tile(const float* __restrict__ A,
                                              const float* __restrict__ Bp,
                                              float* __restrict__ C,
                                              int lda, int ldb, int ldc,
                                              int bm, int bn, int kTiles) {
    // Padded stride 132: (k*132 + m) % 32 == (4k + m) % 32 -> conflict-free
    // for the fragment access pattern (k in 0..3 within quad, m in 0..7).
    __shared__ uint32_t As[16][132]; // As[k][m], tf32
    __shared__ uint32_t Bs[16][132]; // Bs[k][n], tf32

    const int tid = threadIdx.x;
    const int lane = tid & 31;
    const int w = tid >> 5;
    const int wr = w >> 1;      // 0..3  (warp row)
    const int wc = w & 1;       // 0..1  (warp col)
    const int gid = lane >> 2;  // 0..7
    const int tig = lane & 3;   // 0..3

    float acc[2][8][4];
#pragma unroll
    for (int i = 0; i < 2; i++)
#pragma unroll
        for (int j = 0; j < 8; j++)
#pragma unroll
            for (int e = 0; e < 4; e++) acc[i][j][e] = 0.0f;

    float4 ra[2], rb[2];

    // ---- global load helpers (register staging) ----
    auto loadA = [&](int t) {
#pragma unroll
        for (int l = 0; l < 2; l++) {
            const int idx = tid * 2 + l;
            const int row = idx >> 2;            // 0..127
            const int kc = (idx & 3) << 2;       // 0,4,8,12
            ra[l] = *reinterpret_cast<const float4*>(
                A + (size_t)(bm + row) * lda + t * 16 + kc);
        }
    };
    auto loadB = [&](int t) {
#pragma unroll
        for (int l = 0; l < 2; l++) {
            const int idx = tid * 2 + l;
            if (!TRANS_B) {
                const int kr = idx >> 5;         // 0..15
                const int nc = (idx & 31) << 2;  // 0..124
                rb[l] = *reinterpret_cast<const float4*>(
                    Bp + (size_t)(t * 16 + kr) * ldb + bn + nc);
            } else {
                const int nrow = idx >> 2;       // 0..127
                const int kc = (idx & 3) << 2;
                rb[l] = *reinterpret_cast<const float4*>(
                    Bp + (size_t)(bn + nrow) * ldb + t * 16 + kc);
            }
        }
    };
    auto storeAB = [&]() {
#pragma unroll
        for (int l = 0; l < 2; l++) {
            const int idx = tid * 2 + l;
            {
                const int row = idx >> 2;
                const int kc = (idx & 3) << 2;
                As[kc + 0][row] = f2tf32(ra[l].x);
                As[kc + 1][row] = f2tf32(ra[l].y);
                As[kc + 2][row] = f2tf32(ra[l].z);
                As[kc + 3][row] = f2tf32(ra[l].w);
            }
            if (!TRANS_B) {
                const int kr = idx >> 5;
                const int nc = (idx & 31) << 2;
                Bs[kr][nc + 0] = f2tf32(rb[l].x);
                Bs[kr][nc + 1] = f2tf32(rb[l].y);
                Bs[kr][nc + 2] = f2tf32(rb[l].z);
                Bs[kr][nc + 3] = f2tf32(rb[l].w);
            } else {
                const int nrow = idx >> 2;
                const int kc = (idx & 3) << 2;
                Bs[kc + 0][nrow] = f2tf32(rb[l].x);
                Bs[kc + 1][nrow] = f2tf32(rb[l].y);
                Bs[kc + 2][nrow] = f2tf32(rb[l].z);
                Bs[kc + 3][nrow] = f2tf32(rb[l].w);
            }
        }
    };

    loadA(0);
    loadB(0);

    for (int t = 0; t < kTiles; ++t) {
        storeAB();
        __syncthreads();
        if (t + 1 < kTiles) {
            loadA(t + 1);
            loadB(t + 1);
        }

        // compute on the tile in smem
#pragma unroll
        for (int ks = 0; ks < 2; ks++) {
            const int k0 = ks * 8;
            uint32_t af[2][4];
#pragma unroll
            for (int i = 0; i < 2; i++) {
                const int m0 = wr * 32 + i * 16 + gid;
                af[i][0] = As[k0 + tig][m0];
                af[i][1] = As[k0 + tig][m0 + 8];
                af[i][2] = As[k0 + tig + 4][m0];
                af[i][3] = As[k0 + tig + 4][m0 + 8];
            }
            uint32_t bf[8][2];
#pragma unroll
            for (int j = 0; j < 8; j++) {
                const int n0 = wc * 64 + j * 8 + gid;
                bf[j][0] = Bs[k0 + tig][n0];
                bf[j][1] = Bs[k0 + tig + 4][n0];
            }
#pragma unroll
            for (int i = 0; i < 2; i++)
#pragma unroll
                for (int j = 0; j < 8; j++) mma_tf32(acc[i][j], af[i], bf[j]);
        }
        __syncthreads();
    }

    // Epilogue
#pragma unroll
    for (int i = 0; i < 2; i++) {
        const int mrow = bm + wr * 32 + i * 16 + gid;
#pragma unroll
        for (int j = 0; j < 8; j++) {
            const int col = bn + wc * 64 + j * 8 + 2 * tig;
            float2 v0 = make_float2(acc[i][j][0], acc[i][j][1]);
            float2 v1 = make_float2(acc[i][j][2], acc[i][j][3]);
            *reinterpret_cast<float2*>(C + (size_t)mrow * ldc + col) = v0;
            *reinterpret_cast<float2*>(C + (size_t)(mrow + 8) * ldc + col) = v1;
        }
    }
}

// ---------------------------------------------------------------------------
// Kernel 1: fused QKV projection. X[8192,1024] @ W[1024,1024] for 3 weights.
// ---------------------------------------------------------------------------
__global__ __launch_bounds__(256) void proj_kernel(
    const float* __restrict__ X,
    const float* __restrict__ Wq,
    const float* __restrict__ Wk,
    const float* __restrict__ Wv) {
    const float* W = (blockIdx.z == 0) ? Wq : (blockIdx.z == 1) ? Wk : Wv;
    float* C = (blockIdx.z == 0) ? g_q : (blockIdx.z == 1) ? g_k : g_v;
    mma_gemm_tile<false>(X, W, C, D, D, D,
                         blockIdx.y * 128, blockIdx.x * 128, D / 16);
}

// ---------------------------------------------------------------------------
// Kernel 2: scores S[b] = Q[b] @ K[b]^T (NT). Skip tiles above the diagonal.
// ---------------------------------------------------------------------------
__global__ __launch_bounds__(256) void scores_kernel() {
    const int qm = blockIdx.y;
    const int kn = blockIdx.x;
    if (kn > qm) return;
    const int b = blockIdx.z;
    const float* Q = g_q + (size_t)b * T * D;
    const float* Kp = g_k + (size_t)b * T * D;
    float* S = g_p + (size_t)b * T * T;
    mma_gemm_tile<true>(Q, Kp, S, D, D, T, qm * 128, kn * 128, D / 16);
}

// ---------------------------------------------------------------------------
// Kernel 3: row softmax, in place on g_p. Row (b,q): valid range k in [0, q].
// Scale 1/sqrt(D)=1/32 pre-softmax. Writes exact zeros for k > q so the PV
// GEMM needs no masking.
// ---------------------------------------------------------------------------
__global__ __launch_bounds__(256) void softmax_kernel() {
    __shared__ float buf[T];
    __shared__ float red[256];

    const int row = blockIdx.x;
    const int b = row / T;
    const int q = row % T;
    float* S = g_p + (size_t)b * T * T + (size_t)q * T;

    const int tid = threadIdx.x;
    const int n = q + 1;
    const float scale = 0.03125f; // 1/sqrt(1024)

    float m = -INFINITY;
    for (int k = tid; k < n; k += 256) m = fmaxf(m, S[k] * scale);
    red[tid] = m;
    __syncthreads();
    for (int s = 128; s > 0; s >>= 1) {
        if (tid < s) red[tid] = fmaxf(red[tid], red[tid + s]);
        __syncthreads();
    }
    m = red[0];
    __syncthreads();

    float lsum = 0.0f;
    for (int k = tid; k < n; k += 256) {
        const float e = expf(S[k] * scale - m);
        buf[k] = e;
        lsum += e;
    }
    red[tid] = lsum;
    __syncthreads();
    for (int s = 128; s > 0; s >>= 1) {
        if (tid < s) red[tid] += red[tid + s];
        __syncthreads();
    }
    const float inv = 1.0f / red[0];
    __syncthreads();

    for (int k = tid; k < T; k += 256)
        S[k] = (k < n) ? buf[k] * inv : 0.0f;
}

// ---------------------------------------------------------------------------
// Kernel 4: O[b] = P[b] @ V[b] (NN), k-loop truncated at the diagonal.
// ---------------------------------------------------------------------------
__global__ __launch_bounds__(256) void pv_kernel(float* __restrict__ O) {
    const int b = blockIdx.z;
    const int qm = blockIdx.y;
    const float* P = g_p + (size_t)b * T * T;
    const float* V = g_v + (size_t)b * T * D;
    float* Cb = O + (size_t)b * T * D;
    const int kTiles = (qm + 1) * 8; // (qm+1)*128/16
    mma_gemm_tile<false>(P, V, Cb, T, D, D, qm * 128, blockIdx.x * 128,
                         kTiles);
}

// ---------------------------------------------------------------------------
extern "C" void kernel_launch(void* const* d_in, const int* in_sizes, int n_in,
                              void* d_out, int out_size) {
    (void)in_sizes; (void)n_in; (void)out_size;
    const float* X  = (const float*)d_in[0];
    const float* Wq = (const float*)d_in[1];
    const float* Wk = (const float*)d_in[2];
    const float* Wv = (const float*)d_in[3];
    float* O = (float*)d_out;

    dim3 blk(256);
    proj_kernel<<<dim3(D / 128, MPROJ / 128, 3), blk>>>(X, Wq, Wk, Wv);
    scores_kernel<<<dim3(T / 128, T / 128, B), blk>>>();
    softmax_kernel<<<dim3(B * T), blk>>>();
    pv_kernel<<<dim3(D / 128, T / 128, B), blk>>>(O);
}

// round 4
// speedup vs baseline: 3.4064x; 1.6545x over previous
#include <cuda_runtime.h>
#include <math.h>
#include <stdint.h>

// ---------------------------------------------------------------------------
// Problem constants
// ---------------------------------------------------------------------------
namespace {
constexpr int B = 4;
constexpr int T = 2048;
constexpr int D = 1024;      // D_IN == D_OUT
constexpr int MPROJ = B * T; // 8192

// Scratch (allocation-free: __device__ globals)
__device__ float g_x[(size_t)MPROJ * D];  // 32 MB tf32-rounded input
__device__ float g_wq[(size_t)D * D];     // 4 MB tf32-rounded weights
__device__ float g_wk[(size_t)D * D];
__device__ float g_wv[(size_t)D * D];
__device__ float g_q[(size_t)B * T * D];  // 32 MB (tf32 bits)
__device__ float g_k[(size_t)B * T * D];  // 32 MB (tf32 bits)
__device__ float g_v[(size_t)B * T * D];  // 32 MB (tf32 bits)
__device__ float g_p[(size_t)B * T * T];  // 64 MB scores -> probs (tf32 bits)
} // namespace

// ---------------------------------------------------------------------------
// Helpers
// ---------------------------------------------------------------------------
__device__ __forceinline__ uint32_t smem_u32(const void* p) {
    uint32_t a;
    asm("{ .reg .u64 t; cvta.to.shared.u64 t, %1; cvt.u32.u64 %0, t; }"
        : "=r"(a) : "l"(p));
    return a;
}

__device__ __forceinline__ uint32_t f2tf32(float x) {
    uint32_t r;
    asm("cvt.rna.tf32.f32 %0, %1;" : "=r"(r) : "f"(x));
    return r;
}

__device__ __forceinline__ void cp16(uint32_t dst, const void* src) {
    asm volatile("cp.async.cg.shared.global [%0], [%1], 16;"
                 :: "r"(dst), "l"(src) : "memory");
}
#define CP_COMMIT() asm volatile("cp.async.commit_group;" ::: "memory")
#define CP_WAIT(N)  asm volatile("cp.async.wait_group %0;" :: "n"(N) : "memory")

__device__ __forceinline__ void mma_tf32(float c[4], const uint32_t a[4],
                                         const uint32_t b[2]) {
    asm volatile(
        "mma.sync.aligned.m16n8k8.row.col.f32.tf32.tf32.f32 "
        "{%0,%1,%2,%3}, {%4,%5,%6,%7}, {%8,%9}, {%0,%1,%2,%3};"
        : "+f"(c[0]), "+f"(c[1]), "+f"(c[2]), "+f"(c[3])
        : "r"(a[0]), "r"(a[1]), "r"(a[2]), "r"(a[3]), "r"(b[0]), "r"(b[1]));
}

// ---------------------------------------------------------------------------
// tf32 mma.sync GEMM core. CTA tile 128x128, BK=16, 128 threads (4 warps),
// warp tile 64x64 (warp grid 2x2). cp.async 4-stage pipeline; all operands
// already tf32-rounded in global memory (no cvt in the hot loop).
//   TRANS_B = false: C[m,n] += A[m,k] * Bp[k,n]   (Bp row-major [K,N])
//   TRANS_B = true : C[m,n] += A[m,k] * Bp[n,k]   (Bp row-major [N,K])
// SMEM layouts (words):
//   As[m][k]: row stride 20  (128 x 16 + 4 pad)   -> frag loads conflict-free
//   Bs TRANS [n][k]: row stride 20
//   Bs NN    [k][n]: row stride 136 (16 x 128 + 8 pad)
// Stage = 5120 words (20 KB); 4 stages = 80 KB dynamic smem.
// ---------------------------------------------------------------------------
constexpr int STAGES = 4;
constexpr int STAGE_WORDS = 5120;
constexpr int SMEM_BYTES = STAGES * STAGE_WORDS * 4; // 81920

template <bool TRANS_B, bool EPI_CVT>
__device__ __forceinline__ void tc_gemm(const float* __restrict__ A,
                                        const float* __restrict__ Bp,
                                        float* __restrict__ C,
                                        int lda, int ldb, int ldc,
                                        int bm, int bn, int nChunks) {
    extern __shared__ float sm[];
    const uint32_t smem_base = smem_u32(sm);

    const int tid = threadIdx.x;
    const int lane = tid & 31;
    const int wid = tid >> 5;
    const int wr = wid >> 1;     // 0..1
    const int wc = wid & 1;      // 0..1
    const int gid = lane >> 2;   // 0..7
    const int tig = lane & 3;    // 0..3

    auto issue = [&](int chunk, int buf) {
        const int k0 = chunk * 16;
        const uint32_t sA = smem_base + (uint32_t)buf * (STAGE_WORDS * 4);
        const uint32_t sB = sA + 10240;
#pragma unroll
        for (int l = 0; l < 4; l++) {
            const int idx = tid + l * 128;
            const int m = idx >> 2, k4 = idx & 3;
            cp16(sA + (uint32_t)(m * 20 + 4 * k4) * 4,
                 A + (size_t)(bm + m) * lda + k0 + 4 * k4);
        }
#pragma unroll
        for (int l = 0; l < 4; l++) {
            const int idx = tid + l * 128;
            if (TRANS_B) {
                const int n = idx >> 2, k4 = idx & 3;
                cp16(sB + (uint32_t)(n * 20 + 4 * k4) * 4,
                     Bp + (size_t)(bn + n) * ldb + k0 + 4 * k4);
            } else {
                const int k = idx >> 5, n4 = idx & 31;
                cp16(sB + (uint32_t)(k * 136 + 4 * n4) * 4,
                     Bp + (size_t)(k0 + k) * ldb + bn + 4 * n4);
            }
        }
    };

    float acc[4][8][4];
#pragma unroll
    for (int i = 0; i < 4; i++)
#pragma unroll
        for (int j = 0; j < 8; j++)
#pragma unroll
            for (int e = 0; e < 4; e++) acc[i][j][e] = 0.0f;

    // Prologue: fill STAGES-1 stages (nChunks >= 8 always here)
#pragma unroll
    for (int s = 0; s < STAGES - 1; s++) {
        issue(s, s);
        CP_COMMIT();
    }

    for (int t = 0; t < nChunks; t++) {
        CP_WAIT(STAGES - 2);
        __syncthreads();

        const float* As = sm + (t & (STAGES - 1)) * STAGE_WORDS;
        const float* Bs = As + 2560;

        // Prefetch chunk t+STAGES-1 into the stage consumed at t-1.
        if (t + STAGES - 1 < nChunks)
            issue(t + STAGES - 1, (t + STAGES - 1) & (STAGES - 1));
        CP_COMMIT();

#pragma unroll
        for (int kk = 0; kk < 16; kk += 8) {
            uint32_t af[4][4];
#pragma unroll
            for (int i = 0; i < 4; i++) {
                const int m0 = wr * 64 + i * 16 + gid;
                af[i][0] = __float_as_uint(As[m0 * 20 + kk + tig]);
                af[i][1] = __float_as_uint(As[(m0 + 8) * 20 + kk + tig]);
                af[i][2] = __float_as_uint(As[m0 * 20 + kk + tig + 4]);
                af[i][3] = __float_as_uint(As[(m0 + 8) * 20 + kk + tig + 4]);
            }
            uint32_t bf[8][2];
#pragma unroll
            for (int j = 0; j < 8; j++) {
                const int n0 = wc * 64 + j * 8 + gid;
                if (TRANS_B) {
                    bf[j][0] = __float_as_uint(Bs[n0 * 20 + kk + tig]);
                    bf[j][1] = __float_as_uint(Bs[n0 * 20 + kk + tig + 4]);
                } else {
                    bf[j][0] = __float_as_uint(Bs[(kk + tig) * 136 + n0]);
                    bf[j][1] = __float_as_uint(Bs[(kk + tig + 4) * 136 + n0]);
                }
            }
#pragma unroll
            for (int i = 0; i < 4; i++)
#pragma unroll
                for (int j = 0; j < 8; j++) mma_tf32(acc[i][j], af[i], bf[j]);
        }
    }

    // Epilogue
#pragma unroll
    for (int i = 0; i < 4; i++) {
        const int m = bm + wr * 64 + i * 16 + gid;
#pragma unroll
        for (int j = 0; j < 8; j++) {
            const int col = bn + wc * 64 + j * 8 + 2 * tig;
            float* r0 = C + (size_t)m * ldc + col;
            float* r1 = C + (size_t)(m + 8) * ldc + col;
            if (EPI_CVT) {
                uint2 u0 = make_uint2(f2tf32(acc[i][j][0]), f2tf32(acc[i][j][1]));
                uint2 u1 = make_uint2(f2tf32(acc[i][j][2]), f2tf32(acc[i][j][3]));
                *reinterpret_cast<uint2*>(r0) = u0;
                *reinterpret_cast<uint2*>(r1) = u1;
            } else {
                *reinterpret_cast<float2*>(r0) =
                    make_float2(acc[i][j][0], acc[i][j][1]);
                *reinterpret_cast<float2*>(r1) =
                    make_float2(acc[i][j][2], acc[i][j][3]);
            }
        }
    }
}

// ---------------------------------------------------------------------------
// Kernel 0: elementwise tf32 pre-round of X and the three weights.
// ---------------------------------------------------------------------------
__global__ __launch_bounds__(256) void cvt_kernel(const float4* __restrict__ src,
                                                  int which, int n4) {
    float* dstf = (which == 0) ? g_x : (which == 1) ? g_wq
                 : (which == 2) ? g_wk : g_wv;
    uint4* dst = reinterpret_cast<uint4*>(dstf);
    const int stride = gridDim.x * blockDim.x;
    for (int i = blockIdx.x * blockDim.x + threadIdx.x; i < n4; i += stride) {
        const float4 v = src[i];
        uint4 u;
        u.x = f2tf32(v.x); u.y = f2tf32(v.y);
        u.z = f2tf32(v.z); u.w = f2tf32(v.w);
        dst[i] = u;
    }
}

// ---------------------------------------------------------------------------
// Kernel 1: fused QKV projection (NN), epilogue rounds outputs to tf32.
// grid: (N/128=8, M/128=64, 3), block 128
// ---------------------------------------------------------------------------
__global__ __launch_bounds__(128) void proj_kernel() {
    const float* W = (blockIdx.z == 0) ? g_wq : (blockIdx.z == 1) ? g_wk : g_wv;
    float* C = (blockIdx.z == 0) ? g_q : (blockIdx.z == 1) ? g_k : g_v;
    tc_gemm<false, true>(g_x, W, C, D, D, D, blockIdx.y * 128,
                         blockIdx.x * 128, D / 16);
}

// ---------------------------------------------------------------------------
// Kernel 2: scores S[b] = Q[b] @ K[b]^T (NT). Skip tiles above the diagonal.
// ---------------------------------------------------------------------------
__global__ __launch_bounds__(128) void scores_kernel() {
    const int qm = blockIdx.y;
    const int kn = blockIdx.x;
    if (kn > qm) return;
    const int b = blockIdx.z;
    const float* Q = g_q + (size_t)b * T * D;
    const float* Kp = g_k + (size_t)b * T * D;
    float* S = g_p + (size_t)b * T * T;
    tc_gemm<true, false>(Q, Kp, S, D, D, T, qm * 128, kn * 128, D / 16);
}

// ---------------------------------------------------------------------------
// Kernel 3: row softmax, in place on g_p, vectorized + warp shuffles.
// Writes tf32-rounded probs; exact zeros for k > q.
// ---------------------------------------------------------------------------
__global__ __launch_bounds__(256) void softmax_kernel() {
    __shared__ float buf[T];      // exp values
    __shared__ float redm[8];
    __shared__ float reds[8];

    const int row = blockIdx.x;
    const int b = row >> 11;
    const int q = row & 2047;
    float* S = g_p + (size_t)b * T * T + (size_t)q * T;

    const int tid = threadIdx.x;
    const int lane = tid & 31;
    const int wid = tid >> 5;
    const int n = q + 1;
    const int nw4 = (n + 3) >> 2;
    const float scale = 0.03125f; // 1/sqrt(1024)
    const float4* S4 = reinterpret_cast<const float4*>(S);

    // Pass 1: raw max over valid entries
    float m = -1e30f;
    for (int j = tid; j < nw4; j += 256) {
        const float4 v = S4[j];
        const int k = 4 * j;
        if (k + 0 < n) m = fmaxf(m, v.x);
        if (k + 1 < n) m = fmaxf(m, v.y);
        if (k + 2 < n) m = fmaxf(m, v.z);
        if (k + 3 < n) m = fmaxf(m, v.w);
    }
#pragma unroll
    for (int s = 16; s > 0; s >>= 1)
        m = fmaxf(m, __shfl_xor_sync(0xffffffffu, m, s));
    if (lane == 0) redm[wid] = m;
    __syncthreads();
    float mAll = redm[0];
#pragma unroll
    for (int w = 1; w < 8; w++) mAll = fmaxf(mAll, redm[w]);
    const float mS = mAll * scale;

    // Pass 2: exp + sum
    float lsum = 0.0f;
    float4* buf4 = reinterpret_cast<float4*>(buf);
    for (int j = tid; j < nw4; j += 256) {
        const float4 v = S4[j];
        const int k = 4 * j;
        float4 e;
        e.x = (k + 0 < n) ? __expf(fmaf(v.x, scale, -mS)) : 0.0f;
        e.y = (k + 1 < n) ? __expf(fmaf(v.y, scale, -mS)) : 0.0f;
        e.z = (k + 2 < n) ? __expf(fmaf(v.z, scale, -mS)) : 0.0f;
        e.w = (k + 3 < n) ? __expf(fmaf(v.w, scale, -mS)) : 0.0f;
        buf4[j] = e;
        lsum += e.x + e.y + e.z + e.w;
    }
#pragma unroll
    for (int s = 16; s > 0; s >>= 1)
        lsum += __shfl_xor_sync(0xffffffffu, lsum, s);
    if (lane == 0) reds[wid] = lsum;
    __syncthreads();
    float tot = 0.0f;
#pragma unroll
    for (int w = 0; w < 8; w++) tot += reds[w];
    const float inv = 1.0f / tot;

    // Pass 3: write tf32-rounded probs; zero masked tail (full T width)
    uint4* O4 = reinterpret_cast<uint4*>(S);
    for (int j = tid; j < T / 4; j += 256) {
        const int k = 4 * j;
        uint4 u;
        u.x = (k + 0 < n) ? f2tf32(buf[k + 0] * inv) : 0u;
        u.y = (k + 1 < n) ? f2tf32(buf[k + 1] * inv) : 0u;
        u.z = (k + 2 < n) ? f2tf32(buf[k + 2] * inv) : 0u;
        u.w = (k + 3 < n) ? f2tf32(buf[k + 3] * inv) : 0u;
        O4[j] = u;
    }
}

// ---------------------------------------------------------------------------
// Kernel 4: O[b] = P[b] @ V[b] (NN), k-loop truncated at the diagonal.
// ---------------------------------------------------------------------------
__global__ __launch_bounds__(128) void pv_kernel(float* __restrict__ O) {
    const int b = blockIdx.z;
    const int qm = blockIdx.y;
    const float* P = g_p + (size_t)b * T * T;
    const float* V = g_v + (size_t)b * T * D;
    float* Cb = O + (size_t)b * T * D;
    const int nChunks = (qm + 1) * 8; // (qm+1)*128/16
    tc_gemm<false, false>(P, V, Cb, T, D, D, qm * 128, blockIdx.x * 128,
                          nChunks);
}

// ---------------------------------------------------------------------------
extern "C" void kernel_launch(void* const* d_in, const int* in_sizes, int n_in,
                              void* d_out, int out_size) {
    (void)in_sizes; (void)n_in; (void)out_size;
    const float4* X  = (const float4*)d_in[0];
    const float4* Wq = (const float4*)d_in[1];
    const float4* Wk = (const float4*)d_in[2];
    const float4* Wv = (const float4*)d_in[3];
    float* O = (float*)d_out;

    // Idempotent, capture-safe attribute sets (no stream ops).
    cudaFuncSetAttribute(proj_kernel,
                         cudaFuncAttributeMaxDynamicSharedMemorySize,
                         SMEM_BYTES);
    cudaFuncSetAttribute(scores_kernel,
                         cudaFuncAttributeMaxDynamicSharedMemorySize,
                         SMEM_BYTES);
    cudaFuncSetAttribute(pv_kernel,
                         cudaFuncAttributeMaxDynamicSharedMemorySize,
                         SMEM_BYTES);

    cvt_kernel<<<1024, 256>>>(X, 0, MPROJ * D / 4);
    cvt_kernel<<<256, 256>>>(Wq, 1, D * D / 4);
    cvt_kernel<<<256, 256>>>(Wk, 2, D * D / 4);
    cvt_kernel<<<256, 256>>>(Wv, 3, D * D / 4);

    dim3 blk(128);
    proj_kernel<<<dim3(D / 128, MPROJ / 128, 3), blk, SMEM_BYTES>>>();
    scores_kernel<<<dim3(T / 128, T / 128, B), blk, SMEM_BYTES>>>();
    softmax_kernel<<<dim3(B * T), 256>>>();
    pv_kernel<<<dim3(D / 128, T / 128, B), blk, SMEM_BYTES>>>(O);
}

// round 5
// speedup vs baseline: 3.6297x; 1.0656x over previous
#include <cuda_runtime.h>
#include <math.h>
#include <stdint.h>

// ---------------------------------------------------------------------------
// Problem constants
// ---------------------------------------------------------------------------
namespace {
constexpr int B = 4;
constexpr int T = 2048;
constexpr int D = 1024;      // D_IN == D_OUT
constexpr int MPROJ = B * T; // 8192

// Scratch (allocation-free: __device__ globals)
__device__ float g_x[(size_t)MPROJ * D];  // 32 MB tf32-rounded input
__device__ float g_wq[(size_t)D * D];     // 4 MB tf32-rounded weights
__device__ float g_wk[(size_t)D * D];
__device__ float g_wv[(size_t)D * D];
__device__ float g_q[(size_t)B * T * D];  // 32 MB (tf32 bits)
__device__ float g_k[(size_t)B * T * D];  // 32 MB (tf32 bits)
__device__ float g_v[(size_t)B * T * D];  // 32 MB (tf32 bits)
__device__ float g_p[(size_t)B * T * T];  // 64 MB scores -> probs (tf32 bits)
} // namespace

// ---------------------------------------------------------------------------
// Helpers
// ---------------------------------------------------------------------------
__device__ __forceinline__ uint32_t smem_u32(const void* p) {
    uint32_t a;
    asm("{ .reg .u64 t; cvta.to.shared.u64 t, %1; cvt.u32.u64 %0, t; }"
        : "=r"(a) : "l"(p));
    return a;
}

__device__ __forceinline__ uint32_t f2tf32(float x) {
    uint32_t r;
    asm("cvt.rna.tf32.f32 %0, %1;" : "=r"(r) : "f"(x));
    return r;
}

__device__ __forceinline__ void cp16(uint32_t dst, const void* src) {
    asm volatile("cp.async.cg.shared.global [%0], [%1], 16;"
                 :: "r"(dst), "l"(src) : "memory");
}
#define CP_COMMIT() asm volatile("cp.async.commit_group;" ::: "memory")
#define CP_WAIT(N)  asm volatile("cp.async.wait_group %0;" :: "n"(N) : "memory")

__device__ __forceinline__ void mma_tf32(float c[4], const uint32_t a[4],
                                         const uint32_t b[2]) {
    asm volatile(
        "mma.sync.aligned.m16n8k8.row.col.f32.tf32.tf32.f32 "
        "{%0,%1,%2,%3}, {%4,%5,%6,%7}, {%8,%9}, {%0,%1,%2,%3};"
        : "+f"(c[0]), "+f"(c[1]), "+f"(c[2]), "+f"(c[3])
        : "r"(a[0]), "r"(a[1]), "r"(a[2]), "r"(a[3]), "r"(b[0]), "r"(b[1]));
}

// ---------------------------------------------------------------------------
// tf32 mma.sync GEMM core. CTA tile 128x128, BK=16, 128 threads (4 warps),
// warp tile 64x64 (warp grid 2x2). cp.async 3-stage pipeline (60 KB smem ->
// 3 CTAs/SM); all operands already tf32-rounded in global memory.
//   TRANS_B = false: C[m,n] += A[m,k] * Bp[k,n]   (Bp row-major [K,N])
//   TRANS_B = true : C[m,n] += A[m,k] * Bp[n,k]   (Bp row-major [N,K])
// SMEM layouts (words):
//   As[m][k]: row stride 20  (128 x 16 + 4 pad)   -> frag loads conflict-free
//   Bs TRANS [n][k]: row stride 20
//   Bs NN    [k][n]: row stride 136 (16 x 128 + 8 pad)
// Stage = 5120 words (20 KB); 3 stages = 60 KB dynamic smem.
// ---------------------------------------------------------------------------
constexpr int STAGES = 3;
constexpr int STAGE_WORDS = 5120;
constexpr int SMEM_BYTES = STAGES * STAGE_WORDS * 4; // 61440

template <bool TRANS_B, bool EPI_CVT>
__device__ __forceinline__ void tc_gemm(const float* __restrict__ A,
                                        const float* __restrict__ Bp,
                                        float* __restrict__ C,
                                        int lda, int ldb, int ldc,
                                        int bm, int bn, int nChunks) {
    extern __shared__ float sm[];
    const uint32_t smem_base = smem_u32(sm);

    const int tid = threadIdx.x;
    const int lane = tid & 31;
    const int wid = tid >> 5;
    const int wr = wid >> 1;     // 0..1
    const int wc = wid & 1;      // 0..1
    const int gid = lane >> 2;   // 0..7
    const int tig = lane & 3;    // 0..3

    auto issue = [&](int chunk, int buf) {
        const int k0 = chunk * 16;
        const uint32_t sA = smem_base + (uint32_t)buf * (STAGE_WORDS * 4);
        const uint32_t sB = sA + 10240;
#pragma unroll
        for (int l = 0; l < 4; l++) {
            const int idx = tid + l * 128;
            const int m = idx >> 2, k4 = idx & 3;
            cp16(sA + (uint32_t)(m * 20 + 4 * k4) * 4,
                 A + (size_t)(bm + m) * lda + k0 + 4 * k4);
        }
#pragma unroll
        for (int l = 0; l < 4; l++) {
            const int idx = tid + l * 128;
            if (TRANS_B) {
                const int n = idx >> 2, k4 = idx & 3;
                cp16(sB + (uint32_t)(n * 20 + 4 * k4) * 4,
                     Bp + (size_t)(bn + n) * ldb + k0 + 4 * k4);
            } else {
                const int k = idx >> 5, n4 = idx & 31;
                cp16(sB + (uint32_t)(k * 136 + 4 * n4) * 4,
                     Bp + (size_t)(k0 + k) * ldb + bn + 4 * n4);
            }
        }
    };

    float acc[4][8][4];
#pragma unroll
    for (int i = 0; i < 4; i++)
#pragma unroll
        for (int j = 0; j < 8; j++)
#pragma unroll
            for (int e = 0; e < 4; e++) acc[i][j][e] = 0.0f;

    // Prologue: fill STAGES-1 stages (nChunks >= 8 always here)
#pragma unroll
    for (int s = 0; s < STAGES - 1; s++) {
        issue(s, s);
        CP_COMMIT();
    }

    int buf = 0;
    for (int t = 0; t < nChunks; t++) {
        CP_WAIT(STAGES - 2);
        __syncthreads();

        const float* As = sm + buf * STAGE_WORDS;
        const float* Bs = As + 2560;

        // Prefetch chunk t+STAGES-1 into the stage consumed at t-1.
        if (t + STAGES - 1 < nChunks) {
            int pbuf = buf + STAGES - 1;
            if (pbuf >= STAGES) pbuf -= STAGES;
            issue(t + STAGES - 1, pbuf);
        }
        CP_COMMIT();

#pragma unroll
        for (int kk = 0; kk < 16; kk += 8) {
            uint32_t af[4][4];
#pragma unroll
            for (int i = 0; i < 4; i++) {
                const int m0 = wr * 64 + i * 16 + gid;
                af[i][0] = __float_as_uint(As[m0 * 20 + kk + tig]);
                af[i][1] = __float_as_uint(As[(m0 + 8) * 20 + kk + tig]);
                af[i][2] = __float_as_uint(As[m0 * 20 + kk + tig + 4]);
                af[i][3] = __float_as_uint(As[(m0 + 8) * 20 + kk + tig + 4]);
            }
            uint32_t bf[8][2];
#pragma unroll
            for (int j = 0; j < 8; j++) {
                const int n0 = wc * 64 + j * 8 + gid;
                if (TRANS_B) {
                    bf[j][0] = __float_as_uint(Bs[n0 * 20 + kk + tig]);
                    bf[j][1] = __float_as_uint(Bs[n0 * 20 + kk + tig + 4]);
                } else {
                    bf[j][0] = __float_as_uint(Bs[(kk + tig) * 136 + n0]);
                    bf[j][1] = __float_as_uint(Bs[(kk + tig + 4) * 136 + n0]);
                }
            }
#pragma unroll
            for (int i = 0; i < 4; i++)
#pragma unroll
                for (int j = 0; j < 8; j++) mma_tf32(acc[i][j], af[i], bf[j]);
        }
        if (++buf == STAGES) buf = 0;
    }

    // Epilogue
#pragma unroll
    for (int i = 0; i < 4; i++) {
        const int m = bm + wr * 64 + i * 16 + gid;
#pragma unroll
        for (int j = 0; j < 8; j++) {
            const int col = bn + wc * 64 + j * 8 + 2 * tig;
            float* r0 = C + (size_t)m * ldc + col;
            float* r1 = C + (size_t)(m + 8) * ldc + col;
            if (EPI_CVT) {
                uint2 u0 = make_uint2(f2tf32(acc[i][j][0]), f2tf32(acc[i][j][1]));
                uint2 u1 = make_uint2(f2tf32(acc[i][j][2]), f2tf32(acc[i][j][3]));
                *reinterpret_cast<uint2*>(r0) = u0;
                *reinterpret_cast<uint2*>(r1) = u1;
            } else {
                *reinterpret_cast<float2*>(r0) =
                    make_float2(acc[i][j][0], acc[i][j][1]);
                *reinterpret_cast<float2*>(r1) =
                    make_float2(acc[i][j][2], acc[i][j][3]);
            }
        }
    }
}

// ---------------------------------------------------------------------------
// Kernel 0: elementwise tf32 pre-round of X and the three weights.
// ---------------------------------------------------------------------------
__global__ __launch_bounds__(256) void cvt_kernel(const float4* __restrict__ src,
                                                  int which, int n4) {
    float* dstf = (which == 0) ? g_x : (which == 1) ? g_wq
                 : (which == 2) ? g_wk : g_wv;
    uint4* dst = reinterpret_cast<uint4*>(dstf);
    const int stride = gridDim.x * blockDim.x;
    for (int i = blockIdx.x * blockDim.x + threadIdx.x; i < n4; i += stride) {
        const float4 v = src[i];
        uint4 u;
        u.x = f2tf32(v.x); u.y = f2tf32(v.y);
        u.z = f2tf32(v.z); u.w = f2tf32(v.w);
        dst[i] = u;
    }
}

// ---------------------------------------------------------------------------
// Kernel 1: fused QKV projection (NN), epilogue rounds outputs to tf32.
// grid: (N/128=8, M/128=64, 3), block 128
// ---------------------------------------------------------------------------
__global__ __launch_bounds__(128) void proj_kernel() {
    const float* W = (blockIdx.z == 0) ? g_wq : (blockIdx.z == 1) ? g_wk : g_wv;
    float* C = (blockIdx.z == 0) ? g_q : (blockIdx.z == 1) ? g_k : g_v;
    tc_gemm<false, true>(g_x, W, C, D, D, D, blockIdx.y * 128,
                         blockIdx.x * 128, D / 16);
}

// ---------------------------------------------------------------------------
// Kernel 2: scores S[b] = Q[b] @ K[b]^T (NT). Skip tiles above the diagonal.
// ---------------------------------------------------------------------------
__global__ __launch_bounds__(128) void scores_kernel() {
    const int qm = blockIdx.y;
    const int kn = blockIdx.x;
    if (kn > qm) return;
    const int b = blockIdx.z;
    const float* Q = g_q + (size_t)b * T * D;
    const float* Kp = g_k + (size_t)b * T * D;
    float* S = g_p + (size_t)b * T * T;
    tc_gemm<true, false>(Q, Kp, S, D, D, T, qm * 128, kn * 128, D / 16);
}

// ---------------------------------------------------------------------------
// Kernel 3: row softmax, in place on g_p, vectorized + warp shuffles.
// Writes tf32-rounded probs up to the end of the diagonal 128-block only
// (the PV kernel never reads beyond it); zeros inside that range for k > q.
// ---------------------------------------------------------------------------
__global__ __launch_bounds__(256) void softmax_kernel() {
    __shared__ float buf[T];      // exp values
    __shared__ float redm[8];
    __shared__ float reds[8];

    const int row = blockIdx.x;
    const int b = row >> 11;
    const int q = row & 2047;
    float* S = g_p + (size_t)b * T * T + (size_t)q * T;

    const int tid = threadIdx.x;
    const int lane = tid & 31;
    const int wid = tid >> 5;
    const int n = q + 1;
    const int nup = (((q >> 7) + 1) << 7); // round_up(n, 128)
    const int nw4 = (n + 3) >> 2;
    const float scale = 0.03125f; // 1/sqrt(1024)
    const float4* S4 = reinterpret_cast<const float4*>(S);

    // Pass 1: raw max over valid entries
    float m = -1e30f;
    for (int j = tid; j < nw4; j += 256) {
        const float4 v = S4[j];
        const int k = 4 * j;
        if (k + 0 < n) m = fmaxf(m, v.x);
        if (k + 1 < n) m = fmaxf(m, v.y);
        if (k + 2 < n) m = fmaxf(m, v.z);
        if (k + 3 < n) m = fmaxf(m, v.w);
    }
#pragma unroll
    for (int s = 16; s > 0; s >>= 1)
        m = fmaxf(m, __shfl_xor_sync(0xffffffffu, m, s));
    if (lane == 0) redm[wid] = m;
    __syncthreads();
    float mAll = redm[0];
#pragma unroll
    for (int w = 1; w < 8; w++) mAll = fmaxf(mAll, redm[w]);
    const float mS = mAll * scale;

    // Pass 2: exp + sum
    float lsum = 0.0f;
    float4* buf4 = reinterpret_cast<float4*>(buf);
    for (int j = tid; j < nw4; j += 256) {
        const float4 v = S4[j];
        const int k = 4 * j;
        float4 e;
        e.x = (k + 0 < n) ? __expf(fmaf(v.x, scale, -mS)) : 0.0f;
        e.y = (k + 1 < n) ? __expf(fmaf(v.y, scale, -mS)) : 0.0f;
        e.z = (k + 2 < n) ? __expf(fmaf(v.z, scale, -mS)) : 0.0f;
        e.w = (k + 3 < n) ? __expf(fmaf(v.w, scale, -mS)) : 0.0f;
        buf4[j] = e;
        lsum += e.x + e.y + e.z + e.w;
    }
#pragma unroll
    for (int s = 16; s > 0; s >>= 1)
        lsum += __shfl_xor_sync(0xffffffffu, lsum, s);
    if (lane == 0) reds[wid] = lsum;
    __syncthreads();
    float tot = 0.0f;
#pragma unroll
    for (int w = 0; w < 8; w++) tot += reds[w];
    const float inv = 1.0f / tot;

    // Pass 3: write tf32-rounded probs; zero masked tail only up to nup.
    uint4* O4 = reinterpret_cast<uint4*>(S);
    for (int j = tid; j < (nup >> 2); j += 256) {
        const int k = 4 * j;
        uint4 u;
        u.x = (k + 0 < n) ? f2tf32(buf[k + 0] * inv) : 0u;
        u.y = (k + 1 < n) ? f2tf32(buf[k + 1] * inv) : 0u;
        u.z = (k + 2 < n) ? f2tf32(buf[k + 2] * inv) : 0u;
        u.w = (k + 3 < n) ? f2tf32(buf[k + 3] * inv) : 0u;
        O4[j] = u;
    }
}

// ---------------------------------------------------------------------------
// Kernel 4: O[b] = P[b] @ V[b] (NN), k-loop truncated at the diagonal.
// Longest q-blocks are launched first for wave balance.
// ---------------------------------------------------------------------------
__global__ __launch_bounds__(128) void pv_kernel(float* __restrict__ O) {
    const int b = blockIdx.z;
    const int qm = (gridDim.y - 1) - blockIdx.y; // descending work order
    const float* P = g_p + (size_t)b * T * T;
    const float* V = g_v + (size_t)b * T * D;
    float* Cb = O + (size_t)b * T * D;
    const int nChunks = (qm + 1) * 8; // (qm+1)*128/16
    tc_gemm<false, false>(P, V, Cb, T, D, D, qm * 128, blockIdx.x * 128,
                          nChunks);
}

// ---------------------------------------------------------------------------
extern "C" void kernel_launch(void* const* d_in, const int* in_sizes, int n_in,
                              void* d_out, int out_size) {
    (void)in_sizes; (void)n_in; (void)out_size;
    const float4* X  = (const float4*)d_in[0];
    const float4* Wq = (const float4*)d_in[1];
    const float4* Wk = (const float4*)d_in[2];
    const float4* Wv = (const float4*)d_in[3];
    float* O = (float*)d_out;

    // Idempotent, capture-safe attribute sets (no stream ops).
    cudaFuncSetAttribute(proj_kernel,
                         cudaFuncAttributeMaxDynamicSharedMemorySize,
                         SMEM_BYTES);
    cudaFuncSetAttribute(scores_kernel,
                         cudaFuncAttributeMaxDynamicSharedMemorySize,
                         SMEM_BYTES);
    cudaFuncSetAttribute(pv_kernel,
                         cudaFuncAttributeMaxDynamicSharedMemorySize,
                         SMEM_BYTES);

    cvt_kernel<<<1024, 256>>>(X, 0, MPROJ * D / 4);
    cvt_kernel<<<256, 256>>>(Wq, 1, D * D / 4);
    cvt_kernel<<<256, 256>>>(Wk, 2, D * D / 4);
    cvt_kernel<<<256, 256>>>(Wv, 3, D * D / 4);

    dim3 blk(128);
    proj_kernel<<<dim3(D / 128, MPROJ / 128, 3), blk, SMEM_BYTES>>>();
    scores_kernel<<<dim3(T / 128, T / 128, B), blk, SMEM_BYTES>>>();
    softmax_kernel<<<dim3(B * T), 256>>>();
    pv_kernel<<<dim3(D / 128, T / 128, B), blk, SMEM_BYTES>>>(O);
}

// round 6
// speedup vs baseline: 6.4699x; 1.7825x over previous
#include <cuda_runtime.h>
#include <cuda_fp16.h>
#include <math.h>
#include <stdint.h>

// ---------------------------------------------------------------------------
// Problem constants
// ---------------------------------------------------------------------------
namespace {
constexpr int B = 4;
constexpr int T = 2048;
constexpr int D = 1024;      // D_IN == D_OUT
constexpr int MPROJ = B * T; // 8192

// Scratch (allocation-free: __device__ globals)
__device__ __half g_x [(size_t)MPROJ * D];   // 16 MB  fp16 input
__device__ __half g_wt[3][(size_t)D * D];    // 6 MB   fp16 W^T (n-major)
__device__ __half g_q [(size_t)B * T * D];   // 16 MB
__device__ __half g_k [(size_t)B * T * D];   // 16 MB
__device__ __half g_v [(size_t)B * T * D];   // 16 MB
__device__ __half g_vt[(size_t)B * D * T];   // 16 MB  V^T per batch
__device__ float  g_s [(size_t)B * T * T];   // 64 MB  raw scores (fp32)
__device__ __half g_ph[(size_t)B * T * T];   // 32 MB  probs (fp16)
} // namespace

// ---------------------------------------------------------------------------
// Helpers
// ---------------------------------------------------------------------------
__device__ __forceinline__ uint32_t smem_u32(const void* p) {
    uint32_t a;
    asm("{ .reg .u64 t; cvta.to.shared.u64 t, %1; cvt.u32.u64 %0, t; }"
        : "=r"(a) : "l"(p));
    return a;
}

__device__ __forceinline__ void cp16(uint32_t dst, const void* src) {
    asm volatile("cp.async.cg.shared.global [%0], [%1], 16;"
                 :: "r"(dst), "l"(src) : "memory");
}
#define CP_COMMIT() asm volatile("cp.async.commit_group;" ::: "memory")
#define CP_WAIT(N)  asm volatile("cp.async.wait_group %0;" :: "n"(N) : "memory")

__device__ __forceinline__ void mma_f16(float c[4], const uint32_t a[4],
                                        const uint32_t b[2]) {
    asm volatile(
        "mma.sync.aligned.m16n8k16.row.col.f32.f16.f16.f32 "
        "{%0,%1,%2,%3}, {%4,%5,%6,%7}, {%8,%9}, {%0,%1,%2,%3};"
        : "+f"(c[0]), "+f"(c[1]), "+f"(c[2]), "+f"(c[3])
        : "r"(a[0]), "r"(a[1]), "r"(a[2]), "r"(a[3]), "r"(b[0]), "r"(b[1]));
}

// ---------------------------------------------------------------------------
// fp16 mma.sync GEMM core ("NT": both operands K-major).
//   C[m,n] += A[m,k] * Bp[n,k]
// CTA tile 128x128, BK=32 halves, 256 threads (8 warps, 2x4 grid),
// warp tile 64x32. cp.async 3-stage pipeline; XOR-swizzled smem
// (16-word rows, phys_w = w ^ (((row>>1)&3)<<2)) — conflict-free for the
// 16B async stores and the 4-byte fragment loads.
// Stage = A(8KB) + B(8KB) = 16 KB; 3 stages = 48 KB dynamic smem.
// EPI: 0 = fp32 float2 stores, 1 = fp16 half2 stores.
// ---------------------------------------------------------------------------
constexpr int STAGES = 3;
constexpr int STAGE_WORDS = 4096; // 16 KB / 4
constexpr int SMEM_BYTES = STAGES * STAGE_WORDS * 4; // 49152

template <int EPI>
__device__ __forceinline__ void hgemm(const __half* __restrict__ A,
                                      const __half* __restrict__ Bp,
                                      void* __restrict__ Cv,
                                      int lda, int ldb, int ldc,
                                      int bm, int bn, int nChunks) {
    extern __shared__ float sm[];
    const uint32_t smem_base = smem_u32(sm);

    const int tid = threadIdx.x;
    const int lane = tid & 31;
    const int wid = tid >> 5;
    const int wr = wid >> 2;     // 0..1  (64-row slab)
    const int wc = wid & 3;      // 0..3  (32-col slab)
    const int gid = lane >> 2;   // 0..7
    const int tig = lane & 3;    // 0..3

    auto issue = [&](int chunk, int buf) {
        const int k0 = chunk * 32;
        const uint32_t sA = smem_base + (uint32_t)buf * (STAGE_WORDS * 4);
        const uint32_t sB = sA + 2048 * 4;
#pragma unroll
        for (int l = 0; l < 2; l++) {
            const int idx = tid + l * 256;
            const int m = idx >> 2, c = idx & 3;
            const uint32_t sw = ((m >> 1) & 3) << 2;
            cp16(sA + (uint32_t)(m * 16 + ((4 * c) ^ sw)) * 4,
                 A + (size_t)(bm + m) * lda + k0 + 8 * c);
        }
#pragma unroll
        for (int l = 0; l < 2; l++) {
            const int idx = tid + l * 256;
            const int n = idx >> 2, c = idx & 3;
            const uint32_t sw = ((n >> 1) & 3) << 2;
            cp16(sB + (uint32_t)(n * 16 + ((4 * c) ^ sw)) * 4,
                 Bp + (size_t)(bn + n) * ldb + k0 + 8 * c);
        }
    };

    float acc[4][4][4];
#pragma unroll
    for (int i = 0; i < 4; i++)
#pragma unroll
        for (int j = 0; j < 4; j++)
#pragma unroll
            for (int e = 0; e < 4; e++) acc[i][j][e] = 0.0f;

    // Prologue (nChunks >= 4 always)
#pragma unroll
    for (int s = 0; s < STAGES - 1; s++) {
        issue(s, s);
        CP_COMMIT();
    }

    int buf = 0;
    for (int t = 0; t < nChunks; t++) {
        CP_WAIT(STAGES - 2);
        __syncthreads();

        const uint32_t* sa =
            reinterpret_cast<const uint32_t*>(sm) + buf * STAGE_WORDS;
        const uint32_t* sb = sa + 2048;

        if (t + STAGES - 1 < nChunks) {
            int pbuf = buf + STAGES - 1;
            if (pbuf >= STAGES) pbuf -= STAGES;
            issue(t + STAGES - 1, pbuf);
        }
        CP_COMMIT();

#pragma unroll
        for (int s = 0; s < 2; s++) { // two K=16 steps per 32-half chunk
            const int w0 = 8 * s + tig;
            uint32_t af[4][4];
#pragma unroll
            for (int i = 0; i < 4; i++) {
                const int r0 = wr * 64 + i * 16 + gid;
                const int r1 = r0 + 8;
                const uint32_t s0 = ((r0 >> 1) & 3) << 2;
                const uint32_t s1 = ((r1 >> 1) & 3) << 2;
                af[i][0] = sa[r0 * 16 + (w0 ^ s0)];
                af[i][1] = sa[r1 * 16 + (w0 ^ s1)];
                af[i][2] = sa[r0 * 16 + ((w0 + 4) ^ s0)];
                af[i][3] = sa[r1 * 16 + ((w0 + 4) ^ s1)];
            }
            uint32_t bf[4][2];
#pragma unroll
            for (int j = 0; j < 4; j++) {
                const int n0 = wc * 32 + j * 8 + gid;
                const uint32_t sn = ((n0 >> 1) & 3) << 2;
                bf[j][0] = sb[n0 * 16 + (w0 ^ sn)];
                bf[j][1] = sb[n0 * 16 + ((w0 + 4) ^ sn)];
            }
#pragma unroll
            for (int i = 0; i < 4; i++)
#pragma unroll
                for (int j = 0; j < 4; j++) mma_f16(acc[i][j], af[i], bf[j]);
        }
        if (++buf == STAGES) buf = 0;
    }

    // Epilogue
#pragma unroll
    for (int i = 0; i < 4; i++) {
        const int m = bm + wr * 64 + i * 16 + gid;
#pragma unroll
        for (int j = 0; j < 4; j++) {
            const int col = bn + wc * 32 + j * 8 + 2 * tig;
            if (EPI == 1) {
                __half* Ch = (__half*)Cv;
                *reinterpret_cast<__half2*>(Ch + (size_t)m * ldc + col) =
                    __floats2half2_rn(acc[i][j][0], acc[i][j][1]);
                *reinterpret_cast<__half2*>(Ch + (size_t)(m + 8) * ldc + col) =
                    __floats2half2_rn(acc[i][j][2], acc[i][j][3]);
            } else {
                float* Cf = (float*)Cv;
                *reinterpret_cast<float2*>(Cf + (size_t)m * ldc + col) =
                    make_float2(acc[i][j][0], acc[i][j][1]);
                *reinterpret_cast<float2*>(Cf + (size_t)(m + 8) * ldc + col) =
                    make_float2(acc[i][j][2], acc[i][j][3]);
            }
        }
    }
}

// ---------------------------------------------------------------------------
// Kernel 0a: X fp32 -> fp16
// ---------------------------------------------------------------------------
__global__ __launch_bounds__(256) void cvtx_kernel(const float4* __restrict__ src,
                                                   int n4) {
    uint2* dst = reinterpret_cast<uint2*>(g_x);
    const int stride = gridDim.x * blockDim.x;
    for (int i = blockIdx.x * blockDim.x + threadIdx.x; i < n4; i += stride) {
        const float4 v = src[i];
        __half2 h0 = __floats2half2_rn(v.x, v.y);
        __half2 h1 = __floats2half2_rn(v.z, v.w);
        uint2 u;
        u.x = *reinterpret_cast<uint32_t*>(&h0);
        u.y = *reinterpret_cast<uint32_t*>(&h1);
        dst[i] = u;
    }
}

// ---------------------------------------------------------------------------
// Kernel 0b: W fp32 [k][n] -> fp16 W^T [n][k], 32x32 smem tiles, z = weight.
// ---------------------------------------------------------------------------
__global__ __launch_bounds__(256) void wt_kernel(const float* __restrict__ Wq,
                                                 const float* __restrict__ Wk,
                                                 const float* __restrict__ Wv) {
    __shared__ float tile[32][33];
    const float* W = (blockIdx.z == 0) ? Wq : (blockIdx.z == 1) ? Wk : Wv;
    __half* Wt = g_wt[blockIdx.z];
    const int n0 = blockIdx.x * 32, k0 = blockIdx.y * 32;
    const int c = threadIdx.x & 31, r8 = threadIdx.x >> 5;
#pragma unroll
    for (int r = r8; r < 32; r += 8)
        tile[r][c] = W[(size_t)(k0 + r) * D + n0 + c];
    __syncthreads();
#pragma unroll
    for (int r = r8; r < 32; r += 8)
        Wt[(size_t)(n0 + r) * D + k0 + c] = __float2half_rn(tile[c][r]);
}

// ---------------------------------------------------------------------------
// Kernel 0c: V fp16 [b][t][d] -> V^T [b][d][t]
// ---------------------------------------------------------------------------
__global__ __launch_bounds__(256) void vt_kernel() {
    __shared__ __half tile[32][33];
    const int b = blockIdx.z;
    const __half* V = g_v + (size_t)b * T * D;
    __half* Vt = g_vt + (size_t)b * D * T;
    const int t0 = blockIdx.x * 32, d0 = blockIdx.y * 32;
    const int c = threadIdx.x & 31, r8 = threadIdx.x >> 5;
#pragma unroll
    for (int r = r8; r < 32; r += 8)
        tile[r][c] = V[(size_t)(t0 + r) * D + d0 + c];
    __syncthreads();
#pragma unroll
    for (int r = r8; r < 32; r += 8)
        Vt[(size_t)(d0 + r) * T + t0 + c] = tile[c][r];
}

// ---------------------------------------------------------------------------
// Kernel 1: fused QKV projection: g_x @ g_wt[z]^T -> fp16 Q/K/V.
// ---------------------------------------------------------------------------
__global__ __launch_bounds__(256, 2) void proj_kernel() {
    __half* C = (blockIdx.z == 0) ? g_q : (blockIdx.z == 1) ? g_k : g_v;
    hgemm<1>(g_x, g_wt[blockIdx.z], C, D, D, D, blockIdx.y * 128,
             blockIdx.x * 128, D / 32);
}

// ---------------------------------------------------------------------------
// Kernel 2: scores S[b] = Q[b] @ K[b]^T (fp32 out). Skip above-diagonal tiles.
// ---------------------------------------------------------------------------
__global__ __launch_bounds__(256, 2) void scores_kernel() {
    const int qm = blockIdx.y;
    const int kn = blockIdx.x;
    if (kn > qm) return;
    const int b = blockIdx.z;
    hgemm<0>(g_q + (size_t)b * T * D, g_k + (size_t)b * T * D,
             g_s + (size_t)b * T * T, D, D, T, qm * 128, kn * 128, D / 32);
}

// ---------------------------------------------------------------------------
// Kernel 3: row softmax: g_s fp32 -> g_ph fp16, padded with zeros to the end
// of the diagonal 128-block (all PV reads covered).
// ---------------------------------------------------------------------------
__global__ __launch_bounds__(256) void softmax_kernel() {
    __shared__ float buf[T];
    __shared__ float redm[8];
    __shared__ float reds[8];

    const int row = blockIdx.x;
    const int b = row >> 11;
    const int q = row & 2047;
    const float* S = g_s + (size_t)b * T * T + (size_t)q * T;
    __half2* P2 = reinterpret_cast<__half2*>(g_ph + (size_t)b * T * T +
                                             (size_t)q * T);

    const int tid = threadIdx.x;
    const int lane = tid & 31;
    const int wid = tid >> 5;
    const int n = q + 1;
    const int nup = (((q >> 7) + 1) << 7);
    const int nw4 = (n + 3) >> 2;
    const float scale = 0.03125f; // 1/sqrt(1024)
    const float4* S4 = reinterpret_cast<const float4*>(S);

    float m = -1e30f;
    for (int j = tid; j < nw4; j += 256) {
        const float4 v = S4[j];
        const int k = 4 * j;
        if (k + 0 < n) m = fmaxf(m, v.x);
        if (k + 1 < n) m = fmaxf(m, v.y);
        if (k + 2 < n) m = fmaxf(m, v.z);
        if (k + 3 < n) m = fmaxf(m, v.w);
    }
#pragma unroll
    for (int s = 16; s > 0; s >>= 1)
        m = fmaxf(m, __shfl_xor_sync(0xffffffffu, m, s));
    if (lane == 0) redm[wid] = m;
    __syncthreads();
    float mAll = redm[0];
#pragma unroll
    for (int w = 1; w < 8; w++) mAll = fmaxf(mAll, redm[w]);
    const float mS = mAll * scale;

    float lsum = 0.0f;
    float4* buf4 = reinterpret_cast<float4*>(buf);
    for (int j = tid; j < nw4; j += 256) {
        const float4 v = S4[j];
        const int k = 4 * j;
        float4 e;
        e.x = (k + 0 < n) ? __expf(fmaf(v.x, scale, -mS)) : 0.0f;
        e.y = (k + 1 < n) ? __expf(fmaf(v.y, scale, -mS)) : 0.0f;
        e.z = (k + 2 < n) ? __expf(fmaf(v.z, scale, -mS)) : 0.0f;
        e.w = (k + 3 < n) ? __expf(fmaf(v.w, scale, -mS)) : 0.0f;
        buf4[j] = e;
        lsum += e.x + e.y + e.z + e.w;
    }
#pragma unroll
    for (int s = 16; s > 0; s >>= 1)
        lsum += __shfl_xor_sync(0xffffffffu, lsum, s);
    if (lane == 0) reds[wid] = lsum;
    __syncthreads();
    float tot = 0.0f;
#pragma unroll
    for (int w = 0; w < 8; w++) tot += reds[w];
    const float inv = 1.0f / tot;

    for (int j = tid; j < (nup >> 1); j += 256) {
        const int k = 2 * j;
        const float v0 = (k + 0 < n) ? buf[k + 0] * inv : 0.0f;
        const float v1 = (k + 1 < n) ? buf[k + 1] * inv : 0.0f;
        P2[j] = __floats2half2_rn(v0, v1);
    }
}

// ---------------------------------------------------------------------------
// Kernel 4: O[b] = P[b] @ V[b] = P @ (V^T)^T, k-truncated at the diagonal.
// Longest q-blocks launched first.
// ---------------------------------------------------------------------------
__global__ __launch_bounds__(256, 2) void pv_kernel(float* __restrict__ O) {
    const int b = blockIdx.z;
    const int qm = (gridDim.y - 1) - blockIdx.y;
    hgemm<0>(g_ph + (size_t)b * T * T, g_vt + (size_t)b * D * T,
             O + (size_t)b * T * D, T, T, D, qm * 128, blockIdx.x * 128,
             (qm + 1) * 4);
}

// ---------------------------------------------------------------------------
extern "C" void kernel_launch(void* const* d_in, const int* in_sizes, int n_in,
                              void* d_out, int out_size) {
    (void)in_sizes; (void)n_in; (void)out_size;
    const float4* X  = (const float4*)d_in[0];
    const float*  Wq = (const float*)d_in[1];
    const float*  Wk = (const float*)d_in[2];
    const float*  Wv = (const float*)d_in[3];
    float* O = (float*)d_out;

    cudaFuncSetAttribute(proj_kernel,
                         cudaFuncAttributeMaxDynamicSharedMemorySize,
                         SMEM_BYTES);
    cudaFuncSetAttribute(scores_kernel,
                         cudaFuncAttributeMaxDynamicSharedMemorySize,
                         SMEM_BYTES);
    cudaFuncSetAttribute(pv_kernel,
                         cudaFuncAttributeMaxDynamicSharedMemorySize,
                         SMEM_BYTES);

    cvtx_kernel<<<1024, 256>>>(X, MPROJ * D / 4);
    wt_kernel<<<dim3(D / 32, D / 32, 3), 256>>>(Wq, Wk, Wv);

    proj_kernel<<<dim3(D / 128, MPROJ / 128, 3), 256, SMEM_BYTES>>>();
    vt_kernel<<<dim3(T / 32, D / 32, B), 256>>>();
    scores_kernel<<<dim3(T / 128, T / 128, B), 256, SMEM_BYTES>>>();
    softmax_kernel<<<dim3(B * T), 256>>>();
    pv_kernel<<<dim3(D / 128, T / 128, B), 256, SMEM_BYTES>>>(O);
}